// round 5
// baseline (speedup 1.0000x reference)
#include <cuda_runtime.h>

// SubGraphAvgPool: out[b,g,d] = mean(h[b,g,d], h[b,4g+1..4g+4,d]),  B=16, N=8193, D=512, G=2048.
//
// Persistent grid-stride kernel: 1216 CTAs x 128 threads; each CTA loops over
// (b,g) units with stride gridDim.x (~27 iters). Per iteration: 5 independent
// LDG.128 per thread + 1 STG.128. The loop keeps the DRAM queues continuously
// fed (next iteration's loads overlap this iteration's latency) and avoids the
// ~14 wave-transition ramps of the one-CTA-per-unit launch.
//
// Cache hints (same policy as R2 winner):
//   - child rows >= 2049 (g >= 512): __ldcs  (single-use stream)
//   - child rows 1..2048:            default (re-read later as g-rows)
//   - g-node row:                    __ldcs  (last use, L2 hit)
//   - output:                        __stcs  (never re-read)

static constexpr int B = 16;
static constexpr long long N = 8193;
static constexpr int D = 512;
static constexpr int G = 2048;
static constexpr int DV = D / 4;        // 128 float4 per row
static constexpr int UNITS = B * G;     // 32768
static constexpr int GRID = 1216;       // ~8 CTAs per SM (152 SMs)

__global__ __launch_bounds__(128)
void subgraph_avgpool_kernel(const float* __restrict__ h, float* __restrict__ out) {
    const int dv = threadIdx.x;         // 0 .. 127
    const float4* __restrict__ hbase = reinterpret_cast<const float4*>(h) + dv;
    float4* __restrict__ obase = reinterpret_cast<float4*>(out) + dv;

    for (int u = blockIdx.x; u < UNITS; u += GRID) {
        const int g = u & (G - 1);      // G = 2048 = 2^11
        const int b = u >> 11;

        const float4* __restrict__ hp = hbase + (long long)b * (N * DV);

        // g-node row: last use (L2 hit from its earlier child-read)
        const float4 a0 = __ldcs(hp + (long long)g * DV);

        const float4* p = hp + (long long)(4 * g + 1) * DV;
        float4 a1, a2, a3, a4;
        if (g >= 512) {
            a1 = __ldcs(p);          a2 = __ldcs(p + DV);
            a3 = __ldcs(p + 2 * DV); a4 = __ldcs(p + 3 * DV);
        } else {
            a1 = __ldg(p);           a2 = __ldg(p + DV);
            a3 = __ldg(p + 2 * DV);  a4 = __ldg(p + 3 * DV);
        }

        float4 s;
        s.x = (a0.x + a1.x + a2.x + a3.x + a4.x) * 0.2f;
        s.y = (a0.y + a1.y + a2.y + a3.y + a4.y) * 0.2f;
        s.z = (a0.z + a1.z + a2.z + a3.z + a4.z) * 0.2f;
        s.w = (a0.w + a1.w + a2.w + a3.w + a4.w) * 0.2f;

        __stcs(obase + (long long)u * DV, s);
    }
}

extern "C" void kernel_launch(void* const* d_in, const int* in_sizes, int n_in,
                              void* d_out, int out_size) {
    const float* h = (const float*)d_in[0];
    float* out = (float*)d_out;
    subgraph_avgpool_kernel<<<GRID, 128>>>(h, out);
}